// round 1
// baseline (speedup 1.0000x reference)
#include <cuda_runtime.h>

// Problem constants (fixed by setup_inputs): x[B, T, C], pool over T.
#define PB 32
#define PT 8192
#define PC 256
#define NSPLIT 64                 // T-chunks per batch
#define TCHUNK (PT / NSPLIT)      // 128 timesteps per block
#define TLANES 4                  // time-lanes inside a block
#define ITERS (TCHUNK / TLANES)   // 32 float4 loads per thread
#define C4 (PC / 4)               // 64 float4 per row
#define NMOM 5                    // y, y^2, y^3, y^4, x^p

// Scratch: [B][NSPLIT][NMOM][C] floats = 32*64*5*256*4 = 10.5 MB (L2-resident)
__device__ float g_scratch[PB * NSPLIT * NMOM * PC];

// ---------------------------------------------------------------------------
// Pass 1: per (batch, T-chunk) partial shifted moments.
// Shift y = x - 0.5 keeps all cancellation factors O(1) for uniform-ish data
// while remaining algebraically exact for any input.
// ---------------------------------------------------------------------------
__global__ __launch_bounds__(256)
void hom_pass1(const float* __restrict__ x, const float* __restrict__ p_ptr)
{
    const int b     = blockIdx.y;
    const int chunk = blockIdx.x;
    const int tid   = threadIdx.x;
    const int c4    = tid & (C4 - 1);   // 0..63  channel group
    const int tl    = tid >> 6;         // 0..3   time lane

    const float p = p_ptr[0];
    const bool p_is_one = (p == 1.0f);

    const float4* __restrict__ x4 = reinterpret_cast<const float4*>(x);
    const int t0   = chunk * TCHUNK + tl;
    int idx        = (b * PT + t0) * C4 + c4;   // max ~16.8M, fits int
    const int step = TLANES * C4;

    float4 s1 = make_float4(0.f, 0.f, 0.f, 0.f);
    float4 s2 = s1, s3 = s1, s4 = s1, sp = s1;

    if (p_is_one) {
        #pragma unroll 4
        for (int i = 0; i < ITERS; ++i, idx += step) {
            float4 v = x4[idx];
            {
                float y = v.x - 0.5f, y2 = y * y;
                s1.x += y; s2.x += y2; s3.x += y2 * y; s4.x += y2 * y2;
            }
            {
                float y = v.y - 0.5f, y2 = y * y;
                s1.y += y; s2.y += y2; s3.y += y2 * y; s4.y += y2 * y2;
            }
            {
                float y = v.z - 0.5f, y2 = y * y;
                s1.z += y; s2.z += y2; s3.z += y2 * y; s4.z += y2 * y2;
            }
            {
                float y = v.w - 0.5f, y2 = y * y;
                s1.w += y; s2.w += y2; s3.w += y2 * y; s4.w += y2 * y2;
            }
        }
        // sp stays zero; pass 2 derives grp = E[y] + 0.5 when p==1.
    } else {
        #pragma unroll 2
        for (int i = 0; i < ITERS; ++i, idx += step) {
            float4 v = x4[idx];
            {
                float y = v.x - 0.5f, y2 = y * y;
                s1.x += y; s2.x += y2; s3.x += y2 * y; s4.x += y2 * y2;
                sp.x += powf(v.x, p);
            }
            {
                float y = v.y - 0.5f, y2 = y * y;
                s1.y += y; s2.y += y2; s3.y += y2 * y; s4.y += y2 * y2;
                sp.y += powf(v.y, p);
            }
            {
                float y = v.z - 0.5f, y2 = y * y;
                s1.z += y; s2.z += y2; s3.z += y2 * y; s4.z += y2 * y2;
                sp.z += powf(v.z, p);
            }
            {
                float y = v.w - 0.5f, y2 = y * y;
                s1.w += y; s2.w += y2; s3.w += y2 * y; s4.w += y2 * y2;
                sp.w += powf(v.w, p);
            }
        }
    }

    // Reduce the 4 time-lanes through shared memory.
    __shared__ float4 sm[TLANES][NMOM][C4];   // 20 KB
    sm[tl][0][c4] = s1;
    sm[tl][1][c4] = s2;
    sm[tl][2][c4] = s3;
    sm[tl][3][c4] = s4;
    sm[tl][4][c4] = sp;
    __syncthreads();

    float4* __restrict__ sc4 = reinterpret_cast<float4*>(g_scratch);
    const int pbase = ((b * NSPLIT + chunk) * NMOM) * C4;
    for (int w = tid; w < NMOM * C4; w += 256) {
        const int m = w / C4;
        const int c = w - m * C4;
        float4 a = sm[0][m][c];
        float4 bq = sm[1][m][c];
        float4 cq = sm[2][m][c];
        float4 dq = sm[3][m][c];
        float4 r;
        r.x = (a.x + bq.x) + (cq.x + dq.x);
        r.y = (a.y + bq.y) + (cq.y + dq.y);
        r.z = (a.z + bq.z) + (cq.z + dq.z);
        r.w = (a.w + bq.w) + (cq.w + dq.w);
        sc4[pbase + w] = r;
    }
}

// ---------------------------------------------------------------------------
// Pass 2: combine NSPLIT partials per (b, c) with Kahan compensation, then do
// the (cancellation-prone) moment algebra in double. 8192 threads total.
// ---------------------------------------------------------------------------
__global__ __launch_bounds__(256)
void hom_pass2(const float* __restrict__ p_ptr, float* __restrict__ out)
{
    const int b = blockIdx.x;
    const int c = threadIdx.x;

    float s[NMOM]    = {0.f, 0.f, 0.f, 0.f, 0.f};
    float comp[NMOM] = {0.f, 0.f, 0.f, 0.f, 0.f};

    #pragma unroll 4
    for (int ps = 0; ps < NSPLIT; ++ps) {
        const int base = ((b * NSPLIT + ps) * NMOM) * PC + c;
        #pragma unroll
        for (int m = 0; m < NMOM; ++m) {
            float v = g_scratch[base + m * PC];
            float yk = v - comp[m];
            float tk = s[m] + yk;
            comp[m] = (tk - s[m]) - yk;
            s[m] = tk;
        }
    }

    const double invT = 1.0 / (double)PT;
    const double d  = (double)s[0] * invT;   // E[y],  y = x - 0.5
    const double e2 = (double)s[1] * invT;   // E[y^2]
    const double e3 = (double)s[2] * invT;   // E[y^3]
    const double e4 = (double)s[3] * invT;   // E[y^4]

    const double d2  = d * d;
    const double var = e2 - d2;
    const double m3  = e3 - 3.0 * d * e2 + 2.0 * d * d2;
    const double m4  = e4 - 4.0 * d * e3 + 6.0 * d2 * e2 - 3.0 * d2 * d2;

    const float p = p_ptr[0];
    const double grp = (p == 1.0f) ? (d + 0.5) : ((double)s[4] * invT);

    const double stdv = sqrt(var + 1e-6);
    const double st3  = stdv * stdv * stdv;

    float* o = out + b * (4 * PC);
    o[c]           = (float)grp;
    o[PC + c]      = (float)var;
    o[2 * PC + c]  = (float)(m3 / st3);
    o[3 * PC + c]  = (float)(m4 / (st3 * stdv));
}

extern "C" void kernel_launch(void* const* d_in, const int* in_sizes, int n_in,
                              void* d_out, int out_size)
{
    const float* x = (const float*)d_in[0];
    const float* p = (const float*)d_in[1];
    float* out     = (float*)d_out;

    dim3 grid1(NSPLIT, PB);
    hom_pass1<<<grid1, 256>>>(x, p);
    hom_pass2<<<PB, 256>>>(p, out);
}

// round 2
// speedup vs baseline: 1.1410x; 1.1410x over previous
#include <cuda_runtime.h>

// Problem constants (fixed by setup_inputs): x[B, T, C], pool over T.
#define PB 32
#define PT 8192
#define PC 256
#define NSPLIT 64                 // T-chunks per batch
#define TCHUNK (PT / NSPLIT)      // 128 timesteps per block
#define TLANES 4                  // time-lanes inside a block
#define ITERS (TCHUNK / TLANES)   // 32 float4 loads per thread
#define C4 (PC / 4)               // 64 float4 per row
#define NMOM 5                    // y, y^2, y^3, y^4, x^p

// Scratch: [B][NSPLIT][NMOM][C] floats = 32*64*5*256*4 = 10.5 MB (L2-resident)
__device__ float g_scratch[PB * NSPLIT * NMOM * PC];

// ---------------------------------------------------------------------------
// Pass 1: per (batch, T-chunk) partial shifted moments.
// Shift y = x - 0.5 keeps all cancellation factors O(1) for uniform-ish data
// while remaining algebraically exact for any input.
// ---------------------------------------------------------------------------
__global__ __launch_bounds__(256)
void hom_pass1(const float* __restrict__ x, const float* __restrict__ p_ptr)
{
    const int b     = blockIdx.y;
    const int chunk = blockIdx.x;
    const int tid   = threadIdx.x;
    const int c4    = tid & (C4 - 1);   // 0..63  channel group
    const int tl    = tid >> 6;         // 0..3   time lane

    const float p = p_ptr[0];
    const bool p_is_one = (p == 1.0f);

    const float4* __restrict__ x4 = reinterpret_cast<const float4*>(x);
    const int t0   = chunk * TCHUNK + tl;
    int idx        = (b * PT + t0) * C4 + c4;   // max ~16.8M, fits int
    const int step = TLANES * C4;

    float4 s1 = make_float4(0.f, 0.f, 0.f, 0.f);
    float4 s2 = s1, s3 = s1, s4 = s1, sp = s1;

    if (p_is_one) {
        #pragma unroll 4
        for (int i = 0; i < ITERS; ++i, idx += step) {
            float4 v = x4[idx];
            {
                float y = v.x - 0.5f, y2 = y * y;
                s1.x += y; s2.x += y2; s3.x += y2 * y; s4.x += y2 * y2;
            }
            {
                float y = v.y - 0.5f, y2 = y * y;
                s1.y += y; s2.y += y2; s3.y += y2 * y; s4.y += y2 * y2;
            }
            {
                float y = v.z - 0.5f, y2 = y * y;
                s1.z += y; s2.z += y2; s3.z += y2 * y; s4.z += y2 * y2;
            }
            {
                float y = v.w - 0.5f, y2 = y * y;
                s1.w += y; s2.w += y2; s3.w += y2 * y; s4.w += y2 * y2;
            }
        }
        // sp stays zero; pass 2 derives grp = E[y] + 0.5 when p==1.
    } else {
        #pragma unroll 2
        for (int i = 0; i < ITERS; ++i, idx += step) {
            float4 v = x4[idx];
            {
                float y = v.x - 0.5f, y2 = y * y;
                s1.x += y; s2.x += y2; s3.x += y2 * y; s4.x += y2 * y2;
                sp.x += powf(v.x, p);
            }
            {
                float y = v.y - 0.5f, y2 = y * y;
                s1.y += y; s2.y += y2; s3.y += y2 * y; s4.y += y2 * y2;
                sp.y += powf(v.y, p);
            }
            {
                float y = v.z - 0.5f, y2 = y * y;
                s1.z += y; s2.z += y2; s3.z += y2 * y; s4.z += y2 * y2;
                sp.z += powf(v.z, p);
            }
            {
                float y = v.w - 0.5f, y2 = y * y;
                s1.w += y; s2.w += y2; s3.w += y2 * y; s4.w += y2 * y2;
                sp.w += powf(v.w, p);
            }
        }
    }

    // Reduce the 4 time-lanes through shared memory.
    __shared__ float4 sm[TLANES][NMOM][C4];   // 20 KB
    sm[tl][0][c4] = s1;
    sm[tl][1][c4] = s2;
    sm[tl][2][c4] = s3;
    sm[tl][3][c4] = s4;
    sm[tl][4][c4] = sp;
    __syncthreads();

    float4* __restrict__ sc4 = reinterpret_cast<float4*>(g_scratch);
    const int pbase = ((b * NSPLIT + chunk) * NMOM) * C4;
    for (int w = tid; w < NMOM * C4; w += 256) {
        const int m = w / C4;
        const int c = w - m * C4;
        float4 a = sm[0][m][c];
        float4 bq = sm[1][m][c];
        float4 cq = sm[2][m][c];
        float4 dq = sm[3][m][c];
        float4 r;
        r.x = (a.x + bq.x) + (cq.x + dq.x);
        r.y = (a.y + bq.y) + (cq.y + dq.y);
        r.z = (a.z + bq.z) + (cq.z + dq.z);
        r.w = (a.w + bq.w) + (cq.w + dq.w);
        sc4[pbase + w] = r;
    }
}

// ---------------------------------------------------------------------------
// Pass 2: grid (PB, 8). Each block: 32 channels x 8 split-lanes.
// Every lane sums 8 splits x 5 moments in DOUBLE (no serial Kahan chain,
// 40 independent L2-resident loads -> latency fully hidden), then an
// smem tree collapses the 8 lanes and warp 0 finishes the moment algebra.
// ---------------------------------------------------------------------------
#define P2_CG   8                  // channel groups (gridDim.y)
#define P2_CPB  (PC / P2_CG)       // 32 channels per block
#define P2_SL   8                  // split lanes per channel
#define P2_SPL  (NSPLIT / P2_SL)   // 8 splits per lane

__global__ __launch_bounds__(256)
void hom_pass2(const float* __restrict__ p_ptr, float* __restrict__ out)
{
    const int b   = blockIdx.x;
    const int cg  = blockIdx.y;
    const int tid = threadIdx.x;
    const int cl  = tid & (P2_CPB - 1);   // 0..31 channel within group
    const int sl  = tid >> 5;             // 0..7  split lane
    const int c   = cg * P2_CPB + cl;     // global channel

    double s[NMOM] = {0.0, 0.0, 0.0, 0.0, 0.0};

    const float* __restrict__ base0 =
        g_scratch + ((size_t)(b * NSPLIT + sl * P2_SPL) * NMOM) * PC + c;
    #pragma unroll
    for (int i = 0; i < P2_SPL; ++i) {
        const float* bp = base0 + (size_t)i * NMOM * PC;
        #pragma unroll
        for (int m = 0; m < NMOM; ++m)
            s[m] += (double)bp[m * PC];
    }

    __shared__ double sm[P2_SL][NMOM][P2_CPB];   // 10 KB
    #pragma unroll
    for (int m = 0; m < NMOM; ++m)
        sm[sl][m][cl] = s[m];
    __syncthreads();

    if (sl == 0) {
        double t[NMOM];
        #pragma unroll
        for (int m = 0; m < NMOM; ++m) {
            double acc = sm[0][m][cl];
            #pragma unroll
            for (int k = 1; k < P2_SL; ++k)
                acc += sm[k][m][cl];
            t[m] = acc;
        }

        const double invT = 1.0 / (double)PT;
        const double d  = t[0] * invT;   // E[y],  y = x - 0.5
        const double e2 = t[1] * invT;   // E[y^2]
        const double e3 = t[2] * invT;   // E[y^3]
        const double e4 = t[3] * invT;   // E[y^4]

        const double d2  = d * d;
        const double var = e2 - d2;
        const double m3  = e3 - 3.0 * d * e2 + 2.0 * d * d2;
        const double m4  = e4 - 4.0 * d * e3 + 6.0 * d2 * e2 - 3.0 * d2 * d2;

        const float p = p_ptr[0];
        const double grp = (p == 1.0f) ? (d + 0.5) : (t[4] * invT);

        const double stdv = sqrt(var + 1e-6);
        const double st3  = stdv * stdv * stdv;

        float* o = out + b * (4 * PC);
        o[c]          = (float)grp;
        o[PC + c]     = (float)var;
        o[2 * PC + c] = (float)(m3 / st3);
        o[3 * PC + c] = (float)(m4 / (st3 * stdv));
    }
}

extern "C" void kernel_launch(void* const* d_in, const int* in_sizes, int n_in,
                              void* d_out, int out_size)
{
    const float* x = (const float*)d_in[0];
    const float* p = (const float*)d_in[1];
    float* out     = (float*)d_out;

    dim3 grid1(NSPLIT, PB);
    hom_pass1<<<grid1, 256>>>(x, p);

    dim3 grid2(PB, P2_CG);
    hom_pass2<<<grid2, 256>>>(p, out);
}

// round 3
// speedup vs baseline: 1.2739x; 1.1165x over previous
#include <cuda_runtime.h>

// Problem constants (fixed by setup_inputs): x[B, T, C], pool over T.
#define PB 32
#define PT 8192
#define PC 256
#define NSPLIT 64                 // T-chunks per batch
#define TCHUNK (PT / NSPLIT)      // 128 timesteps per block
#define TLANES 4                  // time-lanes inside a block
#define ITERS (TCHUNK / TLANES)   // 32 float4 loads per thread
#define C4 (PC / 4)               // 64 float4 per row
#define NMOM 5                    // y, y^2, y^3, y^4, x^p

// Scratch: [B][NSPLIT][NMOM][C] floats = 32*64*5*256*4 = 10.5 MB
__device__ float g_scratch[PB * NSPLIT * NMOM * PC];

// ---------------------------------------------------------------------------
// Pass 1: per (batch, T-chunk) partial shifted moments.
// Shift y = x - 0.5 keeps all cancellation factors O(1) for uniform-ish data
// while remaining algebraically exact for any input.
// ---------------------------------------------------------------------------
__global__ __launch_bounds__(256)
void hom_pass1(const float* __restrict__ x, const float* __restrict__ p_ptr)
{
    const int b     = blockIdx.y;
    const int chunk = blockIdx.x;
    const int tid   = threadIdx.x;
    const int c4    = tid & (C4 - 1);   // 0..63  channel group
    const int tl    = tid >> 6;         // 0..3   time lane

    const float p = p_ptr[0];
    const bool p_is_one = (p == 1.0f);

    const float4* __restrict__ x4 = reinterpret_cast<const float4*>(x);
    const int t0   = chunk * TCHUNK + tl;
    int idx        = (b * PT + t0) * C4 + c4;   // max ~16.8M, fits int
    const int step = TLANES * C4;

    float4 s1 = make_float4(0.f, 0.f, 0.f, 0.f);
    float4 s2 = s1, s3 = s1, s4 = s1, sp = s1;

    if (p_is_one) {
        #pragma unroll 4
        for (int i = 0; i < ITERS; ++i, idx += step) {
            float4 v = x4[idx];
            {
                float y = v.x - 0.5f, y2 = y * y;
                s1.x += y; s2.x += y2; s3.x += y2 * y; s4.x += y2 * y2;
            }
            {
                float y = v.y - 0.5f, y2 = y * y;
                s1.y += y; s2.y += y2; s3.y += y2 * y; s4.y += y2 * y2;
            }
            {
                float y = v.z - 0.5f, y2 = y * y;
                s1.z += y; s2.z += y2; s3.z += y2 * y; s4.z += y2 * y2;
            }
            {
                float y = v.w - 0.5f, y2 = y * y;
                s1.w += y; s2.w += y2; s3.w += y2 * y; s4.w += y2 * y2;
            }
        }
        // sp stays zero; pass 2 derives grp = E[y] + 0.5 when p==1.
    } else {
        #pragma unroll 2
        for (int i = 0; i < ITERS; ++i, idx += step) {
            float4 v = x4[idx];
            {
                float y = v.x - 0.5f, y2 = y * y;
                s1.x += y; s2.x += y2; s3.x += y2 * y; s4.x += y2 * y2;
                sp.x += powf(v.x, p);
            }
            {
                float y = v.y - 0.5f, y2 = y * y;
                s1.y += y; s2.y += y2; s3.y += y2 * y; s4.y += y2 * y2;
                sp.y += powf(v.y, p);
            }
            {
                float y = v.z - 0.5f, y2 = y * y;
                s1.z += y; s2.z += y2; s3.z += y2 * y; s4.z += y2 * y2;
                sp.z += powf(v.z, p);
            }
            {
                float y = v.w - 0.5f, y2 = y * y;
                s1.w += y; s2.w += y2; s3.w += y2 * y; s4.w += y2 * y2;
                sp.w += powf(v.w, p);
            }
        }
    }

    // Reduce the 4 time-lanes through shared memory.
    __shared__ float4 sm[TLANES][NMOM][C4];   // 20 KB
    sm[tl][0][c4] = s1;
    sm[tl][1][c4] = s2;
    sm[tl][2][c4] = s3;
    sm[tl][3][c4] = s4;
    sm[tl][4][c4] = sp;
    __syncthreads();

    float4* __restrict__ sc4 = reinterpret_cast<float4*>(g_scratch);
    const int pbase = ((b * NSPLIT + chunk) * NMOM) * C4;
    for (int w = tid; w < NMOM * C4; w += 256) {
        const int m = w / C4;
        const int c = w - m * C4;
        float4 a = sm[0][m][c];
        float4 bq = sm[1][m][c];
        float4 cq = sm[2][m][c];
        float4 dq = sm[3][m][c];
        float4 r;
        r.x = (a.x + bq.x) + (cq.x + dq.x);
        r.y = (a.y + bq.y) + (cq.y + dq.y);
        r.z = (a.z + bq.z) + (cq.z + dq.z);
        r.w = (a.w + bq.w) + (cq.w + dq.w);
        sc4[pbase + w] = r;
    }
}

// ---------------------------------------------------------------------------
// Pass 2: grid (PB, 4). Block = 256 threads = 16 float4-channel-groups x 16
// split lanes. All bulk accumulation in fp32 float4 (20 independent LDG.128
// per thread -> high MLP, no FP64 on the hot path). Smem tree collapses the
// 16 lanes; the cancellation-prone moment algebra runs once per channel in
// double (8192 threads total, negligible).
// ---------------------------------------------------------------------------
#define P2_CG    4                  // channel-quarter groups (gridDim.y)
#define P2_C4PB  (C4 / P2_CG)       // 16 float4 groups (64 channels) per block
#define P2_SL    16                 // split lanes
#define P2_SPL   (NSPLIT / P2_SL)   // 4 splits per lane

__global__ __launch_bounds__(256)
void hom_pass2(const float* __restrict__ p_ptr, float* __restrict__ out)
{
    const int b   = blockIdx.x;
    const int cg  = blockIdx.y;
    const int tid = threadIdx.x;
    const int cl  = tid & (P2_C4PB - 1);  // 0..15 float4 group within block
    const int sl  = tid >> 4;             // 0..15 split lane
    const int c4g = cg * P2_C4PB + cl;    // global float4 group (0..63)

    const float4* __restrict__ sc4 = reinterpret_cast<const float4*>(g_scratch);

    float4 acc[NMOM];
    #pragma unroll
    for (int m = 0; m < NMOM; ++m) acc[m] = make_float4(0.f, 0.f, 0.f, 0.f);

    // base index (in float4 units) of split (sl*P2_SPL) for this batch
    const int base0 = ((b * NSPLIT + sl * P2_SPL) * NMOM) * C4 + c4g;
    #pragma unroll
    for (int i = 0; i < P2_SPL; ++i) {
        const int bi = base0 + i * NMOM * C4;
        #pragma unroll
        for (int m = 0; m < NMOM; ++m) {
            float4 v = sc4[bi + m * C4];
            acc[m].x += v.x; acc[m].y += v.y; acc[m].z += v.z; acc[m].w += v.w;
        }
    }

    __shared__ float4 sm[P2_SL][NMOM][P2_C4PB];   // 25.6 KB
    #pragma unroll
    for (int m = 0; m < NMOM; ++m)
        sm[sl][m][cl] = acc[m];
    __syncthreads();

    // Tree-reduce the 16 split lanes: lanes 0..7 add lane+8, then 0..3, ...
    for (int off = P2_SL / 2; off >= 1; off >>= 1) {
        if (sl < off) {
            #pragma unroll
            for (int m = 0; m < NMOM; ++m) {
                float4 a = sm[sl][m][cl];
                float4 bq = sm[sl + off][m][cl];
                a.x += bq.x; a.y += bq.y; a.z += bq.z; a.w += bq.w;
                sm[sl][m][cl] = a;
            }
        }
        __syncthreads();
    }

    // Final algebra: 64 channels per block -> threads 0..63, one channel each.
    if (tid < 4 * P2_C4PB) {
        const int g    = tid >> 2;         // float4 group 0..15
        const int comp = tid & 3;          // component within float4
        const int c    = cg * P2_C4PB * 4 + g * 4 + comp;  // global channel

        double t[NMOM];
        #pragma unroll
        for (int m = 0; m < NMOM; ++m) {
            float4 v = sm[0][m][g];
            t[m] = (double)((comp == 0) ? v.x : (comp == 1) ? v.y
                          : (comp == 2) ? v.z : v.w);
        }

        const double invT = 1.0 / (double)PT;
        const double d  = t[0] * invT;   // E[y],  y = x - 0.5
        const double e2 = t[1] * invT;   // E[y^2]
        const double e3 = t[2] * invT;   // E[y^3]
        const double e4 = t[3] * invT;   // E[y^4]

        const double d2  = d * d;
        const double var = e2 - d2;
        const double m3  = e3 - 3.0 * d * e2 + 2.0 * d * d2;
        const double m4  = e4 - 4.0 * d * e3 + 6.0 * d2 * e2 - 3.0 * d2 * d2;

        const float p = p_ptr[0];
        const double grp = (p == 1.0f) ? (d + 0.5) : (t[4] * invT);

        const double stdv = sqrt(var + 1e-6);
        const double st3  = stdv * stdv * stdv;

        float* o = out + b * (4 * PC);
        o[c]          = (float)grp;
        o[PC + c]     = (float)var;
        o[2 * PC + c] = (float)(m3 / st3);
        o[3 * PC + c] = (float)(m4 / (st3 * stdv));
    }
}

extern "C" void kernel_launch(void* const* d_in, const int* in_sizes, int n_in,
                              void* d_out, int out_size)
{
    const float* x = (const float*)d_in[0];
    const float* p = (const float*)d_in[1];
    float* out     = (float*)d_out;

    dim3 grid1(NSPLIT, PB);
    hom_pass1<<<grid1, 256>>>(x, p);

    dim3 grid2(PB, P2_CG);
    hom_pass2<<<grid2, 256>>>(p, out);
}

// round 4
// speedup vs baseline: 1.4242x; 1.1180x over previous
#include <cuda_runtime.h>

// Problem constants (fixed by setup_inputs): x[B, T, C], pool over T.
#define PB 32
#define PT 8192
#define PC 256
#define NSPLIT 16                 // T-chunks per batch (scratch stays small!)
#define TCHUNK (PT / NSPLIT)      // 512 timesteps per block
#define TLANES 4                  // time-lanes inside a block
#define ITERS (TCHUNK / TLANES)   // 128 float4 loads per thread
#define C4 (PC / 4)               // 64 float4 per row
#define NMOM 5                    // y, y^2, y^3, y^4, x^p

// Scratch: [B][NSPLIT][NMOM][C] floats = 32*16*5*256*4 = 2.6 MB
__device__ float g_scratch[PB * NSPLIT * NMOM * PC];

// ---------------------------------------------------------------------------
// Pass 1: per (batch, T-chunk) partial shifted moments.
// Shift y = x - 0.5 keeps all cancellation factors O(1) for uniform-ish data
// while remaining algebraically exact for any input.
// ---------------------------------------------------------------------------
__global__ __launch_bounds__(256)
void hom_pass1(const float* __restrict__ x, const float* __restrict__ p_ptr)
{
    const int b     = blockIdx.y;
    const int chunk = blockIdx.x;
    const int tid   = threadIdx.x;
    const int c4    = tid & (C4 - 1);   // 0..63  channel group
    const int tl    = tid >> 6;         // 0..3   time lane

    const float p = p_ptr[0];
    const bool p_is_one = (p == 1.0f);

    const float4* __restrict__ x4 = reinterpret_cast<const float4*>(x);
    const int t0   = chunk * TCHUNK + tl;
    int idx        = (b * PT + t0) * C4 + c4;   // max ~16.8M, fits int
    const int step = TLANES * C4;

    float4 s1 = make_float4(0.f, 0.f, 0.f, 0.f);
    float4 s2 = s1, s3 = s1, s4 = s1, sp = s1;

    if (p_is_one) {
        #pragma unroll 4
        for (int i = 0; i < ITERS; ++i, idx += step) {
            float4 v = x4[idx];
            {
                float y = v.x - 0.5f, y2 = y * y;
                s1.x += y; s2.x += y2; s3.x += y2 * y; s4.x += y2 * y2;
            }
            {
                float y = v.y - 0.5f, y2 = y * y;
                s1.y += y; s2.y += y2; s3.y += y2 * y; s4.y += y2 * y2;
            }
            {
                float y = v.z - 0.5f, y2 = y * y;
                s1.z += y; s2.z += y2; s3.z += y2 * y; s4.z += y2 * y2;
            }
            {
                float y = v.w - 0.5f, y2 = y * y;
                s1.w += y; s2.w += y2; s3.w += y2 * y; s4.w += y2 * y2;
            }
        }
        // sp stays zero; pass 2 derives grp = E[y] + 0.5 when p==1.
    } else {
        #pragma unroll 2
        for (int i = 0; i < ITERS; ++i, idx += step) {
            float4 v = x4[idx];
            {
                float y = v.x - 0.5f, y2 = y * y;
                s1.x += y; s2.x += y2; s3.x += y2 * y; s4.x += y2 * y2;
                sp.x += powf(v.x, p);
            }
            {
                float y = v.y - 0.5f, y2 = y * y;
                s1.y += y; s2.y += y2; s3.y += y2 * y; s4.y += y2 * y2;
                sp.y += powf(v.y, p);
            }
            {
                float y = v.z - 0.5f, y2 = y * y;
                s1.z += y; s2.z += y2; s3.z += y2 * y; s4.z += y2 * y2;
                sp.z += powf(v.z, p);
            }
            {
                float y = v.w - 0.5f, y2 = y * y;
                s1.w += y; s2.w += y2; s3.w += y2 * y; s4.w += y2 * y2;
                sp.w += powf(v.w, p);
            }
        }
    }

    // Reduce the 4 time-lanes through shared memory.
    __shared__ float4 sm[TLANES][NMOM][C4];   // 20 KB
    sm[tl][0][c4] = s1;
    sm[tl][1][c4] = s2;
    sm[tl][2][c4] = s3;
    sm[tl][3][c4] = s4;
    sm[tl][4][c4] = sp;
    __syncthreads();

    float4* __restrict__ sc4 = reinterpret_cast<float4*>(g_scratch);
    const int pbase = ((b * NSPLIT + chunk) * NMOM) * C4;
    for (int w = tid; w < NMOM * C4; w += 256) {
        const int m = w / C4;
        const int c = w - m * C4;
        float4 a = sm[0][m][c];
        float4 bq = sm[1][m][c];
        float4 cq = sm[2][m][c];
        float4 dq = sm[3][m][c];
        float4 r;
        r.x = (a.x + bq.x) + (cq.x + dq.x);
        r.y = (a.y + bq.y) + (cq.y + dq.y);
        r.z = (a.z + bq.z) + (cq.z + dq.z);
        r.w = (a.w + bq.w) + (cq.w + dq.w);
        sc4[pbase + w] = r;
    }
}

// ---------------------------------------------------------------------------
// Pass 2: grid (PB, 4). Block = 256 threads = 16 float4-channel-groups x 16
// split lanes; each lane reads exactly ONE split (5 LDG.128). Smem tree
// collapses the 16 lanes; cancellation-prone moment algebra runs once per
// channel in double (negligible).
// ---------------------------------------------------------------------------
#define P2_CG    4                  // channel-quarter groups (gridDim.y)
#define P2_C4PB  (C4 / P2_CG)       // 16 float4 groups (64 channels) per block
#define P2_SL    NSPLIT             // 16 split lanes, one split each

__global__ __launch_bounds__(256)
void hom_pass2(const float* __restrict__ p_ptr, float* __restrict__ out)
{
    const int b   = blockIdx.x;
    const int cg  = blockIdx.y;
    const int tid = threadIdx.x;
    const int cl  = tid & (P2_C4PB - 1);  // 0..15 float4 group within block
    const int sl  = tid >> 4;             // 0..15 split lane
    const int c4g = cg * P2_C4PB + cl;    // global float4 group (0..63)

    const float4* __restrict__ sc4 = reinterpret_cast<const float4*>(g_scratch);

    // One split per lane: 5 independent LDG.128.
    const int base = ((b * NSPLIT + sl) * NMOM) * C4 + c4g;
    float4 acc[NMOM];
    #pragma unroll
    for (int m = 0; m < NMOM; ++m)
        acc[m] = sc4[base + m * C4];

    __shared__ float4 sm[P2_SL][NMOM][P2_C4PB];   // 25.6 KB
    #pragma unroll
    for (int m = 0; m < NMOM; ++m)
        sm[sl][m][cl] = acc[m];
    __syncthreads();

    // Tree-reduce the 16 split lanes.
    for (int off = P2_SL / 2; off >= 1; off >>= 1) {
        if (sl < off) {
            #pragma unroll
            for (int m = 0; m < NMOM; ++m) {
                float4 a = sm[sl][m][cl];
                float4 bq = sm[sl + off][m][cl];
                a.x += bq.x; a.y += bq.y; a.z += bq.z; a.w += bq.w;
                sm[sl][m][cl] = a;
            }
        }
        __syncthreads();
    }

    // Final algebra: 64 channels per block -> threads 0..63, one channel each.
    if (tid < 4 * P2_C4PB) {
        const int g    = tid >> 2;         // float4 group 0..15
        const int comp = tid & 3;          // component within float4
        const int c    = cg * P2_C4PB * 4 + g * 4 + comp;  // global channel

        double t[NMOM];
        #pragma unroll
        for (int m = 0; m < NMOM; ++m) {
            float4 v = sm[0][m][g];
            t[m] = (double)((comp == 0) ? v.x : (comp == 1) ? v.y
                          : (comp == 2) ? v.z : v.w);
        }

        const double invT = 1.0 / (double)PT;
        const double d  = t[0] * invT;   // E[y],  y = x - 0.5
        const double e2 = t[1] * invT;   // E[y^2]
        const double e3 = t[2] * invT;   // E[y^3]
        const double e4 = t[3] * invT;   // E[y^4]

        const double d2  = d * d;
        const double var = e2 - d2;
        const double m3  = e3 - 3.0 * d * e2 + 2.0 * d * d2;
        const double m4  = e4 - 4.0 * d * e3 + 6.0 * d2 * e2 - 3.0 * d2 * d2;

        const float p = p_ptr[0];
        const double grp = (p == 1.0f) ? (d + 0.5) : (t[4] * invT);

        const double stdv = sqrt(var + 1e-6);
        const double st3  = stdv * stdv * stdv;

        float* o = out + b * (4 * PC);
        o[c]          = (float)grp;
        o[PC + c]     = (float)var;
        o[2 * PC + c] = (float)(m3 / st3);
        o[3 * PC + c] = (float)(m4 / (st3 * stdv));
    }
}

extern "C" void kernel_launch(void* const* d_in, const int* in_sizes, int n_in,
                              void* d_out, int out_size)
{
    const float* x = (const float*)d_in[0];
    const float* p = (const float*)d_in[1];
    float* out     = (float*)d_out;

    dim3 grid1(NSPLIT, PB);
    hom_pass1<<<grid1, 256>>>(x, p);

    dim3 grid2(PB, P2_CG);
    hom_pass2<<<grid2, 256>>>(p, out);
}